// round 14
// baseline (speedup 1.0000x reference)
#include <cuda_runtime.h>
#include <cuda_fp16.h>
#include <cstdint>

#define N_NODES 20000
#define N_EDGES 320000
#define F 512
#define DT 0.2f
#define TDECAY 0.1f
#define LN_EPS 1e-5f

// ---- GEMM tiling (single-pass fp16 mma) ----
#define TILE_M 128
#define TILE_N 128
#define KCHUNK 32
#define NCH1 16
#define ROWB 80
#define TSZ (128 * ROWB)         // 10240
#define BUF_SZ (2 * TSZ)         // A + B = 20480
#define SMEM_DYN (2 * BUF_SZ)    // double buffered = 40960

#define NF8 (N_NODES * F / 8)    // 1,280,000
#define WF8 (F * F / 8)          // 32768
#define CONV_N (NF8 + 2 * WF8)
#define SCAN_B 20                // 20 blocks x 1000 nodes
#define NCHUNKS (N_NODES / 4)    // 5000 spmm node-chunks (4 nodes each)

// ---- static device scratch (zero-initialized at module load) ----
__device__ float g_w[N_EDGES];          // exp(+c*ts), unscaled
__device__ float g_degw[N_NODES];
__device__ float g_dinv[N_NODES];
__device__ int   g_cnt[N_NODES];
__device__ int   g_rowptr[N_NODES + 1];
__device__ int   g_cursor[N_NODES];
__device__ int   g_psum[SCAN_B];
__device__ int   g_scan_arrive;
__device__ unsigned g_sp_count;         // persistent-spmm barrier
__device__ unsigned g_sp_gen;           // monotonic generation
__device__ int   g_sp_cur[5];           // per-step work-stealing cursors
__device__ int2  g_edge[N_EDGES];       // {src, DT*ew bits}
__device__ unsigned g_tmax_bits;
// fp16 data (8 halfs per uint4)
__device__ uint4 g_xf16[NF8];
__device__ uint4 g_f16a[NF8];
__device__ uint4 g_f16b[NF8];
__device__ uint4 g_wt16[WF8];
__device__ uint4 g_wr16[WF8];

// ---------------- helpers ----------------
__device__ __forceinline__ uint32_t smem_u32(const void* p) {
    uint32_t a;
    asm("{ .reg .u64 t; cvta.to.shared.u64 t, %1; cvt.u32.u64 %0, t; }" : "=r"(a) : "l"(p));
    return a;
}
__device__ __forceinline__ void ldsm4(unsigned* r, uint32_t addr) {
    asm volatile("ldmatrix.sync.aligned.m8n8.x4.shared.b16 {%0,%1,%2,%3}, [%4];"
                 : "=r"(r[0]), "=r"(r[1]), "=r"(r[2]), "=r"(r[3]) : "r"(addr));
}
__device__ __forceinline__ void mma_f16(float* d, const unsigned* a, unsigned b0, unsigned b1) {
    asm volatile(
        "mma.sync.aligned.m16n8k16.row.col.f32.f16.f16.f32 "
        "{%0,%1,%2,%3}, {%4,%5,%6,%7}, {%8,%9}, {%0,%1,%2,%3};"
        : "+f"(d[0]), "+f"(d[1]), "+f"(d[2]), "+f"(d[3])
        : "r"(a[0]), "r"(a[1]), "r"(a[2]), "r"(a[3]), "r"(b0), "r"(b1));
}
__device__ __forceinline__ void cpa16(uint32_t dst, const void* src, int src_sz) {
    asm volatile("cp.async.cg.shared.global [%0], [%1], 16, %2;"
                 :: "r"(dst), "l"(src), "r"(src_sz));
}
__device__ __forceinline__ void cpa_commit() {
    asm volatile("cp.async.commit_group;" ::: "memory");
}
__device__ __forceinline__ void cpa_wait0() {
    asm volatile("cp.async.wait_group 0;" ::: "memory");
}
__device__ __forceinline__ unsigned pack_f16(float a, float b) {
    __half2 p = __float22half2_rn(make_float2(a, b));
    return *reinterpret_cast<unsigned*>(&p);
}
__device__ __forceinline__ float decode_gt(const void* p) {
    int iv = *(const int*)p;
    if (iv >= 0 && iv < (1 << 24)) return (float)iv;
    return *(const float*)p;
}
__device__ __forceinline__ void accum8(float* acc, uint4 u, float w) {
    float2 f;
    f = __half22float2(*reinterpret_cast<__half2*>(&u.x)); acc[0] += w * f.x; acc[1] += w * f.y;
    f = __half22float2(*reinterpret_cast<__half2*>(&u.y)); acc[2] += w * f.x; acc[3] += w * f.y;
    f = __half22float2(*reinterpret_cast<__half2*>(&u.z)); acc[4] += w * f.x; acc[5] += w * f.y;
    f = __half22float2(*reinterpret_cast<__half2*>(&u.w)); acc[6] += w * f.x; acc[7] += w * f.y;
}
__device__ __forceinline__ uint4 cvt8_f16(float4 v0, float4 v1) {
    uint4 h;
    h.x = pack_f16(v0.x, v0.y);
    h.y = pack_f16(v0.z, v0.w);
    h.z = pack_f16(v1.x, v1.y);
    h.w = pack_f16(v1.z, v1.w);
    return h;
}

// ---- launch 0: zero counters + tmax seed + convert x, W_t, W_r -> fp16 ----
__global__ void k_conv(const float* __restrict__ x, const float* __restrict__ wt,
                       const float* __restrict__ wr, const void* gt_ptr) {
    int i = blockIdx.x * blockDim.x + threadIdx.x;
    if (i < N_NODES) { g_cnt[i] = 0; g_degw[i] = 0.f; }
    if (i == 0) {
        g_tmax_bits = __float_as_uint(decode_gt(gt_ptr));  // ts >= 0: uint order ok
        g_scan_arrive = 0;
    }
    if (i < NF8) {
        g_xf16[i] = cvt8_f16(((const float4*)x)[2 * i], ((const float4*)x)[2 * i + 1]);
    } else if (i < NF8 + WF8) {
        int j = i - NF8;
        g_wt16[j] = cvt8_f16(((const float4*)wt)[2 * j], ((const float4*)wt)[2 * j + 1]);
    } else if (i < CONV_N) {
        int j = i - NF8 - WF8;
        g_wr16[j] = cvt8_f16(((const float4*)wr)[2 * j], ((const float4*)wr)[2 * j + 1]);
    }
}

// ---- launch 1: edge pass (tmax, counts, unscaled degree, unscaled w) ----
__global__ void k_pass1w(const int* __restrict__ ei, const float* __restrict__ ts) {
    int e = blockIdx.x * blockDim.x + threadIdx.x;   // grid covers exactly N_EDGES
    float tse = ts[e];
    unsigned mb = __float_as_uint(tse);
#pragma unroll
    for (int o = 16; o; o >>= 1) mb = max(mb, __shfl_xor_sync(0xffffffffu, mb, o));
    if ((threadIdx.x & 31) == 0) atomicMax(&g_tmax_bits, mb);
    float u = expf(TDECAY * tse);
    g_w[e] = u;
    int dst = ei[N_EDGES + e];
    atomicAdd(&g_cnt[dst], 1);
    atomicAdd(&g_degw[dst], u);
}

// ---- launch 2: fused scan (local scan + cross-block handshake + offsets + dinv) ----
__global__ __launch_bounds__(1024) void k_scan(const void* gt_ptr) {
    __shared__ int sh[1024];
    __shared__ int sps[SCAN_B];
    int b = blockIdx.x, t = threadIdx.x;
    int idx = b * 1000 + t;
    int v = (t < 1000) ? g_cnt[idx] : 0;
    sh[t] = v;
    __syncthreads();
    for (int o = 1; o < 1024; o <<= 1) {
        int x = 0;
        if (t >= o) x = sh[t - o];
        __syncthreads();
        sh[t] += x;
        __syncthreads();
    }
    int local_ex = sh[t] - v;
    if (t == 1023) {
        g_psum[b] = sh[1023];
        __threadfence();
        atomicAdd(&g_scan_arrive, 1);
    }
    if (t == 0) {
        while (atomicAdd(&g_scan_arrive, 0) < SCAN_B) {}
        __threadfence();
    }
    __syncthreads();
    if (t < SCAN_B) sps[t] = g_psum[t];
    __syncthreads();
    if (t < 1000) {
        int off = 0, tot = 0;
#pragma unroll
        for (int q = 0; q < SCAN_B; q++) {
            int p = sps[q];
            if (q < b) off += p;
            tot += p;
        }
        int val = local_ex + off;
        g_rowptr[idx] = val;
        g_cursor[idx] = val;
        if (idx == 0) g_rowptr[N_NODES] = tot;
        float tmax = __uint_as_float(g_tmax_bits);
        float sc = expf(-TDECAY * tmax);
        float self_w = expf(-TDECAY * (tmax - decode_gt(gt_ptr)));
        float totw = g_degw[idx] * sc + self_w;
        g_dinv[idx] = (totw > 0.f) ? (1.f / sqrtf(totw)) : 0.f;
    }
}

// ---- launch 3: CSR fill with fused weights ----
__global__ void k_fill(const int* __restrict__ ei) {
    int e = blockIdx.x * blockDim.x + threadIdx.x;
    if (e >= N_EDGES) return;
    float tmax = __uint_as_float(g_tmax_bits);
    float sc = DT * expf(-TDECAY * tmax);
    int src = ei[e], dst = ei[N_EDGES + e];
    int p = atomicAdd(&g_cursor[dst], 1);
    float ew = g_dinv[src] * g_w[e] * sc * g_dinv[dst];
    g_edge[p] = make_int2(src, __float_as_int(ew));
}

// ---- launch 4: persistent 5-step SpMM with per-step work stealing ----
__device__ __forceinline__ void grid_bar() {
    __threadfence();          // make this thread's hout stores visible
    __syncthreads();
    if (threadIdx.x == 0) {
        unsigned my = atomicAdd(&g_sp_gen, 0u);
        unsigned t = atomicAdd(&g_sp_count, 1u);
        if (t == gridDim.x - 1) {
            g_sp_count = 0;
            __threadfence();
            atomicAdd(&g_sp_gen, 1u);
        } else {
            while (atomicAdd(&g_sp_gen, 0u) == my) __nanosleep(64);
        }
        __threadfence();
    }
    __syncthreads();
}

__global__ __launch_bounds__(256) void k_spmm5(const void* gt_ptr) {
    __shared__ int s_chunk;
    float tmax = __uint_as_float(g_tmax_bits);
    float self_w = expf(-TDECAY * (tmax - decode_gt(gt_ptr)));
    int sub = threadIdx.x >> 6;           // 64-thread group per node
    int t = threadIdx.x & 63;

    for (int step = 0; step < 5; step++) {
        const uint4* __restrict__ hin =
            (step == 0) ? g_xf16 : ((step & 1) ? g_f16a : g_f16b);
        uint4* hout = (step & 1) ? g_f16b : g_f16a;

        for (;;) {
            __syncthreads();
            if (threadIdx.x == 0) s_chunk = atomicAdd(&g_sp_cur[step], 1);
            __syncthreads();
            int c = s_chunk;
            if (c >= NCHUNKS) break;

            int n = c * 4 + sub;
            float dv = g_dinv[n];
            float coef = (1.f - DT) + DT * self_w * dv * dv;

            size_t self_idx = (size_t)n * 64 + t;
            float acc[8];
            {
                uint4 su = hin[self_idx];
                float2 f;
                f = __half22float2(*reinterpret_cast<__half2*>(&su.x)); acc[0] = coef * f.x; acc[1] = coef * f.y;
                f = __half22float2(*reinterpret_cast<__half2*>(&su.y)); acc[2] = coef * f.x; acc[3] = coef * f.y;
                f = __half22float2(*reinterpret_cast<__half2*>(&su.z)); acc[4] = coef * f.x; acc[5] = coef * f.y;
                f = __half22float2(*reinterpret_cast<__half2*>(&su.w)); acc[6] = coef * f.x; acc[7] = coef * f.y;
            }

            int j = g_rowptr[n], end = g_rowptr[n + 1];
            for (; j + 8 <= end; j += 8) {
                int2 e[8]; uint4 u[8];
#pragma unroll
                for (int q = 0; q < 8; q++) e[q] = g_edge[j + q];
#pragma unroll
                for (int q = 0; q < 8; q++) u[q] = hin[(size_t)e[q].x * 64 + t];
#pragma unroll
                for (int q = 0; q < 8; q++) accum8(acc, u[q], __int_as_float(e[q].y));
            }
            for (; j + 2 <= end; j += 2) {
                int2 e0 = g_edge[j], e1 = g_edge[j + 1];
                uint4 u0 = hin[(size_t)e0.x * 64 + t];
                uint4 u1 = hin[(size_t)e1.x * 64 + t];
                accum8(acc, u0, __int_as_float(e0.y));
                accum8(acc, u1, __int_as_float(e1.y));
            }
            if (j < end) {
                int2 e = g_edge[j];
                uint4 u = hin[(size_t)e.x * 64 + t];
                accum8(acc, u, __int_as_float(e.y));
            }

            uint4 o;
            o.x = pack_f16(acc[0], acc[1]);
            o.y = pack_f16(acc[2], acc[3]);
            o.z = pack_f16(acc[4], acc[5]);
            o.w = pack_f16(acc[6], acc[7]);
            hout[self_idx] = o;
        }
        if (step < 4) grid_bar();
    }
}

// ---- chunk loader: A + B fp16 tiles, 128 rows x 32 halfs, cp.async ----
__device__ __forceinline__ void load_chunk(uint32_t sb,
                                           const __half* __restrict__ A,
                                           const __half* __restrict__ B,
                                           int arow0, int brow0, int k0, int t) {
#pragma unroll
    for (int it = 0; it < 2; it++) {
        int s = t + it * 256;
        int row = s >> 2, q = s & 3;
        uint32_t doff = row * ROWB + q * 16;
        int ar = arow0 + row;
        int ok = (ar < N_NODES) ? 16 : 0;
        size_t aoff = (size_t)(ok ? ar : 0) * F + k0 + q * 8;
        size_t boff = (size_t)(brow0 + row) * F + k0 + q * 8;
        cpa16(sb + doff, A + aoff, ok);
        cpa16(sb + TSZ + doff, B + boff, 16);
    }
}

// ---- launch 5: fused dual GEMM fp16: out = relu(h@Wt^T + b) + x@Wr^T ----
// occupancy 2 (NOT 4): the 64-float accumulator file needs ~128 regs; capping at
// 64 regs (occ 4) spills accumulators into the MMA loop — measured regression R8.
__global__ __launch_bounds__(256, 2) void k_gemm2(const float* __restrict__ bias,
                                                  float* __restrict__ out) {
    extern __shared__ char smd[];
    int t = threadIdx.x, lane = t & 31, wid = t >> 5;
    int wm = wid >> 1, wn = wid & 1;
    int bm = blockIdx.x, bn = blockIdx.y;

    int lr8 = lane & 7, lt = lane >> 3;
    int row_off = lr8 + (lt & 1) * 8;
    int col_off = (lt >> 1) * 8;

    const __half* H = (const __half*)g_f16a;     // diffusion output (step 4 -> g_f16a)
    const __half* X = (const __half*)g_xf16;
    const __half* T = (const __half*)g_wt16;
    const __half* R = (const __half*)g_wr16;

    float acc[2][8][4];
#pragma unroll
    for (int i = 0; i < 2; i++)
#pragma unroll
        for (int j = 0; j < 8; j++)
#pragma unroll
            for (int q = 0; q < 4; q++) acc[i][j][q] = 0.f;

    uint32_t sbase = smem_u32(smd);
    int am0 = bm * TILE_M, bn0 = bn * TILE_N;

    load_chunk(sbase, H, T, am0, bn0, 0, t);
    cpa_commit();

    for (int c = 0; c < 2 * NCH1; c++) {
        cpa_wait0();
        __syncthreads();
        if (c + 1 < 2 * NCH1) {
            int cn = c + 1;
            uint32_t nsb = sbase + (cn & 1) * BUF_SZ;
            if (cn < NCH1)
                load_chunk(nsb, H, T, am0, bn0, cn * KCHUNK, t);
            else
                load_chunk(nsb, X, R, am0, bn0, (cn - NCH1) * KCHUNK, t);
            cpa_commit();
        }
        uint32_t sb = sbase + (c & 1) * BUF_SZ;
#pragma unroll
        for (int ks = 0; ks < 2; ks++) {
            unsigned af[2][4];
#pragma unroll
            for (int mt = 0; mt < 2; mt++)
                ldsm4(af[mt], sb + (wm * 32 + mt * 16 + row_off) * ROWB
                                 + (ks * 16 + col_off) * 2);
            unsigned bf[4][4];
#pragma unroll
            for (int pr = 0; pr < 4; pr++)
                ldsm4(bf[pr], sb + TSZ + (wn * 64 + pr * 16 + row_off) * ROWB
                                 + (ks * 16 + col_off) * 2);
#pragma unroll
            for (int mt = 0; mt < 2; mt++)
#pragma unroll
                for (int nt = 0; nt < 8; nt++) {
                    int pr = nt >> 1, h = nt & 1;
                    mma_f16(acc[mt][nt], af[mt], bf[pr][h], bf[pr][h + 2]);
                }
        }
        if (c == NCH1 - 1) {
            // acc = relu(acc + bias); then accumulate x@Wr^T into same registers
            int cb = bn0 + wn * 64 + 2 * (lane & 3);
#pragma unroll
            for (int nt = 0; nt < 8; nt++) {
                float b0 = __ldg(bias + cb + nt * 8);
                float b1 = __ldg(bias + cb + nt * 8 + 1);
#pragma unroll
                for (int mt = 0; mt < 2; mt++) {
                    acc[mt][nt][0] = fmaxf(acc[mt][nt][0] + b0, 0.f);
                    acc[mt][nt][1] = fmaxf(acc[mt][nt][1] + b1, 0.f);
                    acc[mt][nt][2] = fmaxf(acc[mt][nt][2] + b0, 0.f);
                    acc[mt][nt][3] = fmaxf(acc[mt][nt][3] + b1, 0.f);
                }
            }
        }
        __syncthreads();
    }

    int rbase = am0 + wm * 32 + (lane >> 2);
    int cbase = bn0 + wn * 64 + 2 * (lane & 3);
#pragma unroll
    for (int mt = 0; mt < 2; mt++) {
#pragma unroll
        for (int h = 0; h < 2; h++) {
            int row = rbase + mt * 16 + h * 8;
            if (row >= N_NODES) continue;
            float* crow = out + (size_t)row * F;
#pragma unroll
            for (int nt = 0; nt < 8; nt++) {
                int col = cbase + nt * 8;
                *(float2*)(crow + col) = make_float2(acc[mt][nt][2 * h], acc[mt][nt][2 * h + 1]);
            }
        }
    }
}

// ---- launch 6: row LayerNorm in place + spmm cursor reset for next replay ----
__global__ __launch_bounds__(128) void k_ln(float* __restrict__ out,
                                            const float* __restrict__ gamma,
                                            const float* __restrict__ beta) {
    int n = blockIdx.x;
    int t = threadIdx.x;
    if (n == 0 && t < 5) g_sp_cur[t] = 0;   // all consumers upstream of this launch
    float4* row = (float4*)(out + (size_t)n * F);
    float4 v = row[t];
    float s = v.x + v.y + v.z + v.w;
    float q = v.x * v.x + v.y * v.y + v.z * v.z + v.w * v.w;
#pragma unroll
    for (int o = 16; o; o >>= 1) {
        s += __shfl_xor_sync(0xffffffffu, s, o);
        q += __shfl_xor_sync(0xffffffffu, q, o);
    }
    __shared__ float shs[4], shq[4];
    int w = t >> 5, l = t & 31;
    if (l == 0) { shs[w] = s; shq[w] = q; }
    __syncthreads();
    s = shs[0] + shs[1] + shs[2] + shs[3];
    q = shq[0] + shq[1] + shq[2] + shq[3];
    float mu = s * (1.f / F);
    float var = q * (1.f / F) - mu * mu;
    float inv = rsqrtf(var + LN_EPS);
    float4 gv = ((const float4*)gamma)[t];
    float4 bv = ((const float4*)beta)[t];
    v.x = (v.x - mu) * inv * gv.x + bv.x;
    v.y = (v.y - mu) * inv * gv.y + bv.y;
    v.z = (v.z - mu) * inv * gv.z + bv.z;
    v.w = (v.w - mu) * inv * gv.w + bv.w;
    row[t] = v;
}

extern "C" void kernel_launch(void* const* d_in, const int* in_sizes, int n_in,
                              void* d_out, int out_size) {
    const float* x = (const float*)d_in[0];
    const int* ei = (const int*)d_in[1];
    const float* ts = (const float*)d_in[2];
    const float* W_t = (const float*)d_in[3];
    const float* b_t = (const float*)d_in[4];
    const float* W_r = (const float*)d_in[5];
    const float* gamma = (const float*)d_in[6];
    const float* beta = (const float*)d_in[7];
    const void* gt = d_in[8];
    float* out = (float*)d_out;

    // one-time config: smem attr + persistent-spmm grid (guaranteed co-residency)
    static int grid_sp = 0;
    if (!grid_sp) {
        cudaFuncSetAttribute(k_gemm2, cudaFuncAttributeMaxDynamicSharedMemorySize, SMEM_DYN);
        int occ = 0, sms = 0;
        cudaOccupancyMaxActiveBlocksPerMultiprocessor(&occ, k_spmm5, 256, 0);
        cudaDeviceGetAttribute(&sms, cudaDevAttrMultiProcessorCount, 0);
        grid_sp = occ * sms;
        if (grid_sp < 1) grid_sp = 1;
        if (grid_sp > NCHUNKS) grid_sp = NCHUNKS;
    }

    k_conv<<<(CONV_N + 255) / 256, 256>>>(x, W_t, W_r, gt);   // 0
    k_pass1w<<<N_EDGES / 256, 256>>>(ei, ts);                 // 1
    k_scan<<<SCAN_B, 1024>>>(gt);                             // 2
    k_fill<<<N_EDGES / 256, 256>>>(ei);                       // 3
    k_spmm5<<<grid_sp, 256>>>(gt);                            // 4 (5 steps fused)
    dim3 gg((N_NODES + TILE_M - 1) / TILE_M, F / TILE_N);
    k_gemm2<<<gg, 256, SMEM_DYN>>>(b_t, out);                 // 5
    k_ln<<<N_NODES, 128>>>(out, gamma, beta);                 // 6
}

// round 15
// speedup vs baseline: 1.3881x; 1.3881x over previous
#include <cuda_runtime.h>
#include <cuda_fp16.h>
#include <cstdint>

#define N_NODES 20000
#define N_EDGES 320000
#define F 512
#define DT 0.2f
#define TDECAY 0.1f
#define LN_EPS 1e-5f

// ---- GEMM tiling (single-pass fp16 mma) ----
#define TILE_M 128
#define TILE_N 128
#define KCHUNK 32
#define NCH1 16
#define ROWB 80
#define TSZ (128 * ROWB)         // 10240
#define BUF_SZ (2 * TSZ)         // A + B = 20480
#define SMEM_DYN (2 * BUF_SZ)    // double buffered = 40960

#define NF8 (N_NODES * F / 8)    // 1,280,000
#define WF8 (F * F / 8)          // 32768
#define CONV_N (NF8 + 2 * WF8)
#define SCAN_B 20                // 20 blocks x 1000 nodes
#define NCHUNKS (N_NODES / 4)    // 5000 spmm node-chunks (4 nodes each)

// ---- static device scratch (zero-initialized at module load) ----
__device__ float g_w[N_EDGES];          // exp(+c*ts), unscaled
__device__ float g_degw[N_NODES];
__device__ float g_dinv[N_NODES];
__device__ int   g_cnt[N_NODES];
__device__ int   g_rowptr[N_NODES + 1];
__device__ int   g_cursor[N_NODES];
__device__ int   g_psum[SCAN_B];
__device__ int   g_scan_arrive;
__device__ unsigned g_sp_count;         // persistent-spmm barrier (self-resetting)
__device__ unsigned g_sp_gen;           // monotonic generation
__device__ int2  g_edge[N_EDGES];       // {src, DT*ew bits}
__device__ unsigned g_tmax_bits;
// fp16 data (8 halfs per uint4)
__device__ uint4 g_xf16[NF8];
__device__ uint4 g_f16a[NF8];
__device__ uint4 g_f16b[NF8];
__device__ uint4 g_wt16[WF8];
__device__ uint4 g_wr16[WF8];

// ---------------- helpers ----------------
__device__ __forceinline__ uint32_t smem_u32(const void* p) {
    uint32_t a;
    asm("{ .reg .u64 t; cvta.to.shared.u64 t, %1; cvt.u32.u64 %0, t; }" : "=r"(a) : "l"(p));
    return a;
}
__device__ __forceinline__ void ldsm4(unsigned* r, uint32_t addr) {
    asm volatile("ldmatrix.sync.aligned.m8n8.x4.shared.b16 {%0,%1,%2,%3}, [%4];"
                 : "=r"(r[0]), "=r"(r[1]), "=r"(r[2]), "=r"(r[3]) : "r"(addr));
}
__device__ __forceinline__ void mma_f16(float* d, const unsigned* a, unsigned b0, unsigned b1) {
    asm volatile(
        "mma.sync.aligned.m16n8k16.row.col.f32.f16.f16.f32 "
        "{%0,%1,%2,%3}, {%4,%5,%6,%7}, {%8,%9}, {%0,%1,%2,%3};"
        : "+f"(d[0]), "+f"(d[1]), "+f"(d[2]), "+f"(d[3])
        : "r"(a[0]), "r"(a[1]), "r"(a[2]), "r"(a[3]), "r"(b0), "r"(b1));
}
__device__ __forceinline__ void cpa16(uint32_t dst, const void* src, int src_sz) {
    asm volatile("cp.async.cg.shared.global [%0], [%1], 16, %2;"
                 :: "r"(dst), "l"(src), "r"(src_sz));
}
__device__ __forceinline__ void cpa_commit() {
    asm volatile("cp.async.commit_group;" ::: "memory");
}
__device__ __forceinline__ void cpa_wait0() {
    asm volatile("cp.async.wait_group 0;" ::: "memory");
}
__device__ __forceinline__ unsigned pack_f16(float a, float b) {
    __half2 p = __float22half2_rn(make_float2(a, b));
    return *reinterpret_cast<unsigned*>(&p);
}
__device__ __forceinline__ float decode_gt(const void* p) {
    int iv = *(const int*)p;
    if (iv >= 0 && iv < (1 << 24)) return (float)iv;
    return *(const float*)p;
}
__device__ __forceinline__ void accum8(float* acc, uint4 u, float w) {
    float2 f;
    f = __half22float2(*reinterpret_cast<__half2*>(&u.x)); acc[0] += w * f.x; acc[1] += w * f.y;
    f = __half22float2(*reinterpret_cast<__half2*>(&u.y)); acc[2] += w * f.x; acc[3] += w * f.y;
    f = __half22float2(*reinterpret_cast<__half2*>(&u.z)); acc[4] += w * f.x; acc[5] += w * f.y;
    f = __half22float2(*reinterpret_cast<__half2*>(&u.w)); acc[6] += w * f.x; acc[7] += w * f.y;
}
__device__ __forceinline__ uint4 cvt8_f16(float4 v0, float4 v1) {
    uint4 h;
    h.x = pack_f16(v0.x, v0.y);
    h.y = pack_f16(v0.z, v0.w);
    h.z = pack_f16(v1.x, v1.y);
    h.w = pack_f16(v1.z, v1.w);
    return h;
}

// ---- launch 0: zero counters + tmax seed + convert x, W_t, W_r -> fp16 ----
__global__ void k_conv(const float* __restrict__ x, const float* __restrict__ wt,
                       const float* __restrict__ wr, const void* gt_ptr) {
    int i = blockIdx.x * blockDim.x + threadIdx.x;
    if (i < N_NODES) { g_cnt[i] = 0; g_degw[i] = 0.f; }
    if (i == 0) {
        g_tmax_bits = __float_as_uint(decode_gt(gt_ptr));  // ts >= 0: uint order ok
        g_scan_arrive = 0;
    }
    if (i < NF8) {
        g_xf16[i] = cvt8_f16(((const float4*)x)[2 * i], ((const float4*)x)[2 * i + 1]);
    } else if (i < NF8 + WF8) {
        int j = i - NF8;
        g_wt16[j] = cvt8_f16(((const float4*)wt)[2 * j], ((const float4*)wt)[2 * j + 1]);
    } else if (i < CONV_N) {
        int j = i - NF8 - WF8;
        g_wr16[j] = cvt8_f16(((const float4*)wr)[2 * j], ((const float4*)wr)[2 * j + 1]);
    }
}

// ---- launch 1: edge pass (tmax, counts, unscaled degree, unscaled w) ----
__global__ void k_pass1w(const int* __restrict__ ei, const float* __restrict__ ts) {
    int e = blockIdx.x * blockDim.x + threadIdx.x;   // grid covers exactly N_EDGES
    float tse = ts[e];
    unsigned mb = __float_as_uint(tse);
#pragma unroll
    for (int o = 16; o; o >>= 1) mb = max(mb, __shfl_xor_sync(0xffffffffu, mb, o));
    if ((threadIdx.x & 31) == 0) atomicMax(&g_tmax_bits, mb);
    float u = expf(TDECAY * tse);
    g_w[e] = u;
    int dst = ei[N_EDGES + e];
    atomicAdd(&g_cnt[dst], 1);
    atomicAdd(&g_degw[dst], u);
}

// ---- launch 2: fused scan (local scan + cross-block handshake + offsets + dinv) ----
__global__ __launch_bounds__(1024) void k_scan(const void* gt_ptr) {
    __shared__ int sh[1024];
    __shared__ int sps[SCAN_B];
    int b = blockIdx.x, t = threadIdx.x;
    int idx = b * 1000 + t;
    int v = (t < 1000) ? g_cnt[idx] : 0;
    sh[t] = v;
    __syncthreads();
    for (int o = 1; o < 1024; o <<= 1) {
        int x = 0;
        if (t >= o) x = sh[t - o];
        __syncthreads();
        sh[t] += x;
        __syncthreads();
    }
    int local_ex = sh[t] - v;
    if (t == 1023) {
        g_psum[b] = sh[1023];
        __threadfence();
        atomicAdd(&g_scan_arrive, 1);
    }
    if (t == 0) {
        while (atomicAdd(&g_scan_arrive, 0) < SCAN_B) {}
        __threadfence();
    }
    __syncthreads();
    if (t < SCAN_B) sps[t] = g_psum[t];
    __syncthreads();
    if (t < 1000) {
        int off = 0, tot = 0;
#pragma unroll
        for (int q = 0; q < SCAN_B; q++) {
            int p = sps[q];
            if (q < b) off += p;
            tot += p;
        }
        int val = local_ex + off;
        g_rowptr[idx] = val;
        g_cursor[idx] = val;
        if (idx == 0) g_rowptr[N_NODES] = tot;
        float tmax = __uint_as_float(g_tmax_bits);
        float sc = expf(-TDECAY * tmax);
        float self_w = expf(-TDECAY * (tmax - decode_gt(gt_ptr)));
        float totw = g_degw[idx] * sc + self_w;
        g_dinv[idx] = (totw > 0.f) ? (1.f / sqrtf(totw)) : 0.f;
    }
}

// ---- launch 3: CSR fill with fused weights ----
__global__ void k_fill(const int* __restrict__ ei) {
    int e = blockIdx.x * blockDim.x + threadIdx.x;
    if (e >= N_EDGES) return;
    float tmax = __uint_as_float(g_tmax_bits);
    float sc = DT * expf(-TDECAY * tmax);
    int src = ei[e], dst = ei[N_EDGES + e];
    int p = atomicAdd(&g_cursor[dst], 1);
    float ew = g_dinv[src] * g_w[e] * sc * g_dinv[dst];
    g_edge[p] = make_int2(src, __float_as_int(ew));
}

// ---- launch 4: persistent 5-step SpMM, STATIC partition (measured 159.5us) ----
__device__ __forceinline__ void grid_bar() {
    __threadfence();          // make this thread's hout stores visible
    __syncthreads();
    if (threadIdx.x == 0) {
        unsigned my = atomicAdd(&g_sp_gen, 0u);
        unsigned t = atomicAdd(&g_sp_count, 1u);
        if (t == gridDim.x - 1) {
            g_sp_count = 0;
            __threadfence();
            atomicAdd(&g_sp_gen, 1u);
        } else {
            while (atomicAdd(&g_sp_gen, 0u) == my) __nanosleep(64);
        }
        __threadfence();
    }
    __syncthreads();
}

__global__ __launch_bounds__(256) void k_spmm5(const void* gt_ptr) {
    float tmax = __uint_as_float(g_tmax_bits);
    float self_w = expf(-TDECAY * (tmax - decode_gt(gt_ptr)));
    int sub = threadIdx.x >> 6;           // 64-thread group per node
    int t = threadIdx.x & 63;

    for (int step = 0; step < 5; step++) {
        const uint4* __restrict__ hin =
            (step == 0) ? g_xf16 : ((step & 1) ? g_f16a : g_f16b);
        uint4* hout = (step & 1) ? g_f16b : g_f16a;

        for (int c = blockIdx.x; c < NCHUNKS; c += gridDim.x) {
            int n = c * 4 + sub;
            float dv = g_dinv[n];
            float coef = (1.f - DT) + DT * self_w * dv * dv;

            size_t self_idx = (size_t)n * 64 + t;
            float acc[8];
            {
                uint4 su = hin[self_idx];
                float2 f;
                f = __half22float2(*reinterpret_cast<__half2*>(&su.x)); acc[0] = coef * f.x; acc[1] = coef * f.y;
                f = __half22float2(*reinterpret_cast<__half2*>(&su.y)); acc[2] = coef * f.x; acc[3] = coef * f.y;
                f = __half22float2(*reinterpret_cast<__half2*>(&su.z)); acc[4] = coef * f.x; acc[5] = coef * f.y;
                f = __half22float2(*reinterpret_cast<__half2*>(&su.w)); acc[6] = coef * f.x; acc[7] = coef * f.y;
            }

            int j = g_rowptr[n], end = g_rowptr[n + 1];
            for (; j + 8 <= end; j += 8) {
                int2 e[8]; uint4 u[8];
#pragma unroll
                for (int q = 0; q < 8; q++) e[q] = g_edge[j + q];
#pragma unroll
                for (int q = 0; q < 8; q++) u[q] = hin[(size_t)e[q].x * 64 + t];
#pragma unroll
                for (int q = 0; q < 8; q++) accum8(acc, u[q], __int_as_float(e[q].y));
            }
            for (; j + 2 <= end; j += 2) {
                int2 e0 = g_edge[j], e1 = g_edge[j + 1];
                uint4 u0 = hin[(size_t)e0.x * 64 + t];
                uint4 u1 = hin[(size_t)e1.x * 64 + t];
                accum8(acc, u0, __int_as_float(e0.y));
                accum8(acc, u1, __int_as_float(e1.y));
            }
            if (j < end) {
                int2 e = g_edge[j];
                uint4 u = hin[(size_t)e.x * 64 + t];
                accum8(acc, u, __int_as_float(e.y));
            }

            uint4 o;
            o.x = pack_f16(acc[0], acc[1]);
            o.y = pack_f16(acc[2], acc[3]);
            o.z = pack_f16(acc[4], acc[5]);
            o.w = pack_f16(acc[6], acc[7]);
            hout[self_idx] = o;
        }
        if (step < 4) grid_bar();
    }
}

// ---- chunk loader: A + B fp16 tiles, 128 rows x 32 halfs, cp.async ----
__device__ __forceinline__ void load_chunk(uint32_t sb,
                                           const __half* __restrict__ A,
                                           const __half* __restrict__ B,
                                           int arow0, int brow0, int k0, int t) {
#pragma unroll
    for (int it = 0; it < 2; it++) {
        int s = t + it * 256;
        int row = s >> 2, q = s & 3;
        uint32_t doff = row * ROWB + q * 16;
        int ar = arow0 + row;
        int ok = (ar < N_NODES) ? 16 : 0;
        size_t aoff = (size_t)(ok ? ar : 0) * F + k0 + q * 8;
        size_t boff = (size_t)(brow0 + row) * F + k0 + q * 8;
        cpa16(sb + doff, A + aoff, ok);
        cpa16(sb + TSZ + doff, B + boff, 16);
    }
}

// ---- launch 5: fused dual GEMM fp16: out = relu(h@Wt^T + b) + x@Wr^T ----
// occupancy 2 (NOT 4): the 64-float accumulator file needs ~128 regs; capping at
// 64 regs (occ 4) spills accumulators into the MMA loop — measured regression R8.
__global__ __launch_bounds__(256, 2) void k_gemm2(const float* __restrict__ bias,
                                                  float* __restrict__ out) {
    extern __shared__ char smd[];
    int t = threadIdx.x, lane = t & 31, wid = t >> 5;
    int wm = wid >> 1, wn = wid & 1;
    int bm = blockIdx.x, bn = blockIdx.y;

    int lr8 = lane & 7, lt = lane >> 3;
    int row_off = lr8 + (lt & 1) * 8;
    int col_off = (lt >> 1) * 8;

    const __half* H = (const __half*)g_f16a;     // diffusion output (step 4 -> g_f16a)
    const __half* X = (const __half*)g_xf16;
    const __half* T = (const __half*)g_wt16;
    const __half* R = (const __half*)g_wr16;

    float acc[2][8][4];
#pragma unroll
    for (int i = 0; i < 2; i++)
#pragma unroll
        for (int j = 0; j < 8; j++)
#pragma unroll
            for (int q = 0; q < 4; q++) acc[i][j][q] = 0.f;

    uint32_t sbase = smem_u32(smd);
    int am0 = bm * TILE_M, bn0 = bn * TILE_N;

    load_chunk(sbase, H, T, am0, bn0, 0, t);
    cpa_commit();

    for (int c = 0; c < 2 * NCH1; c++) {
        cpa_wait0();
        __syncthreads();
        if (c + 1 < 2 * NCH1) {
            int cn = c + 1;
            uint32_t nsb = sbase + (cn & 1) * BUF_SZ;
            if (cn < NCH1)
                load_chunk(nsb, H, T, am0, bn0, cn * KCHUNK, t);
            else
                load_chunk(nsb, X, R, am0, bn0, (cn - NCH1) * KCHUNK, t);
            cpa_commit();
        }
        uint32_t sb = sbase + (c & 1) * BUF_SZ;
#pragma unroll
        for (int ks = 0; ks < 2; ks++) {
            unsigned af[2][4];
#pragma unroll
            for (int mt = 0; mt < 2; mt++)
                ldsm4(af[mt], sb + (wm * 32 + mt * 16 + row_off) * ROWB
                                 + (ks * 16 + col_off) * 2);
            unsigned bf[4][4];
#pragma unroll
            for (int pr = 0; pr < 4; pr++)
                ldsm4(bf[pr], sb + TSZ + (wn * 64 + pr * 16 + row_off) * ROWB
                                 + (ks * 16 + col_off) * 2);
#pragma unroll
            for (int mt = 0; mt < 2; mt++)
#pragma unroll
                for (int nt = 0; nt < 8; nt++) {
                    int pr = nt >> 1, h = nt & 1;
                    mma_f16(acc[mt][nt], af[mt], bf[pr][h], bf[pr][h + 2]);
                }
        }
        if (c == NCH1 - 1) {
            // acc = relu(acc + bias); then accumulate x@Wr^T into same registers
            int cb = bn0 + wn * 64 + 2 * (lane & 3);
#pragma unroll
            for (int nt = 0; nt < 8; nt++) {
                float b0 = __ldg(bias + cb + nt * 8);
                float b1 = __ldg(bias + cb + nt * 8 + 1);
#pragma unroll
                for (int mt = 0; mt < 2; mt++) {
                    acc[mt][nt][0] = fmaxf(acc[mt][nt][0] + b0, 0.f);
                    acc[mt][nt][1] = fmaxf(acc[mt][nt][1] + b1, 0.f);
                    acc[mt][nt][2] = fmaxf(acc[mt][nt][2] + b0, 0.f);
                    acc[mt][nt][3] = fmaxf(acc[mt][nt][3] + b1, 0.f);
                }
            }
        }
        __syncthreads();
    }

    int rbase = am0 + wm * 32 + (lane >> 2);
    int cbase = bn0 + wn * 64 + 2 * (lane & 3);
#pragma unroll
    for (int mt = 0; mt < 2; mt++) {
#pragma unroll
        for (int h = 0; h < 2; h++) {
            int row = rbase + mt * 16 + h * 8;
            if (row >= N_NODES) continue;
            float* crow = out + (size_t)row * F;
#pragma unroll
            for (int nt = 0; nt < 8; nt++) {
                int col = cbase + nt * 8;
                *(float2*)(crow + col) = make_float2(acc[mt][nt][2 * h], acc[mt][nt][2 * h + 1]);
            }
        }
    }
}

// ---- launch 6: row LayerNorm in place ----
__global__ __launch_bounds__(128) void k_ln(float* __restrict__ out,
                                            const float* __restrict__ gamma,
                                            const float* __restrict__ beta) {
    int n = blockIdx.x;
    int t = threadIdx.x;
    float4* row = (float4*)(out + (size_t)n * F);
    float4 v = row[t];
    float s = v.x + v.y + v.z + v.w;
    float q = v.x * v.x + v.y * v.y + v.z * v.z + v.w * v.w;
#pragma unroll
    for (int o = 16; o; o >>= 1) {
        s += __shfl_xor_sync(0xffffffffu, s, o);
        q += __shfl_xor_sync(0xffffffffu, q, o);
    }
    __shared__ float shs[4], shq[4];
    int w = t >> 5, l = t & 31;
    if (l == 0) { shs[w] = s; shq[w] = q; }
    __syncthreads();
    s = shs[0] + shs[1] + shs[2] + shs[3];
    q = shq[0] + shq[1] + shq[2] + shq[3];
    float mu = s * (1.f / F);
    float var = q * (1.f / F) - mu * mu;
    float inv = rsqrtf(var + LN_EPS);
    float4 gv = ((const float4*)gamma)[t];
    float4 bv = ((const float4*)beta)[t];
    v.x = (v.x - mu) * inv * gv.x + bv.x;
    v.y = (v.y - mu) * inv * gv.y + bv.y;
    v.z = (v.z - mu) * inv * gv.z + bv.z;
    v.w = (v.w - mu) * inv * gv.w + bv.w;
    row[t] = v;
}

extern "C" void kernel_launch(void* const* d_in, const int* in_sizes, int n_in,
                              void* d_out, int out_size) {
    const float* x = (const float*)d_in[0];
    const int* ei = (const int*)d_in[1];
    const float* ts = (const float*)d_in[2];
    const float* W_t = (const float*)d_in[3];
    const float* b_t = (const float*)d_in[4];
    const float* W_r = (const float*)d_in[5];
    const float* gamma = (const float*)d_in[6];
    const float* beta = (const float*)d_in[7];
    const void* gt = d_in[8];
    float* out = (float*)d_out;

    // one-time config: smem attr + persistent-spmm grid (guaranteed co-residency)
    static int grid_sp = 0;
    if (!grid_sp) {
        cudaFuncSetAttribute(k_gemm2, cudaFuncAttributeMaxDynamicSharedMemorySize, SMEM_DYN);
        int occ = 0, sms = 0;
        cudaOccupancyMaxActiveBlocksPerMultiprocessor(&occ, k_spmm5, 256, 0);
        cudaDeviceGetAttribute(&sms, cudaDevAttrMultiProcessorCount, 0);
        grid_sp = occ * sms;
        if (grid_sp < 1) grid_sp = 1;
        if (grid_sp > NCHUNKS) grid_sp = NCHUNKS;
    }

    k_conv<<<(CONV_N + 255) / 256, 256>>>(x, W_t, W_r, gt);   // 0
    k_pass1w<<<N_EDGES / 256, 256>>>(ei, ts);                 // 1
    k_scan<<<SCAN_B, 1024>>>(gt);                             // 2
    k_fill<<<N_EDGES / 256, 256>>>(ei);                       // 3
    k_spmm5<<<grid_sp, 256>>>(gt);                            // 4 (5 steps fused, static)
    dim3 gg((N_NODES + TILE_M - 1) / TILE_M, F / TILE_N);
    k_gemm2<<<gg, 256, SMEM_DYN>>>(b_t, out);                 // 5
    k_ln<<<N_NODES, 128>>>(out, gamma, beta);                 // 6
}

// round 16
// speedup vs baseline: 1.6623x; 1.1976x over previous
#include <cuda_runtime.h>
#include <cuda_fp16.h>
#include <cstdint>

#define N_NODES 20000
#define N_EDGES 320000
#define F 512
#define DT 0.2f
#define TDECAY 0.1f
#define LN_EPS 1e-5f

// ---- GEMM tiling (single-pass fp16 mma) ----
#define TILE_M 128
#define TILE_N 128
#define KCHUNK 32
#define NCH1 16
#define ROWB 80
#define TSZ (128 * ROWB)         // 10240
#define BUF_SZ (2 * TSZ)         // A + B = 20480
#define SMEM_DYN (2 * BUF_SZ)    // double buffered = 40960

#define NF8 (N_NODES * F / 8)    // 1,280,000
#define WF8 (F * F / 8)          // 32768
#define CONV_N (NF8 + 2 * WF8)
#define SCAN_B 20                // 20 blocks x 1000 nodes

// ---- static device scratch (zero-initialized at module load; k_ln re-zeroes per run) ----
__device__ float g_w[N_EDGES];          // exp(+c*ts), unscaled
__device__ float g_degw[N_NODES];
__device__ float g_dinv[N_NODES];
__device__ int   g_cnt[N_NODES];
__device__ int   g_rowptr[N_NODES + 1];
__device__ int   g_cursor[N_NODES];
__device__ int   g_psum[SCAN_B];
__device__ int   g_scan_arrive;
__device__ int2  g_edge[N_EDGES];       // {src, DT*ew bits}
__device__ unsigned g_tmax_bits;
// fp16 data (8 halfs per uint4)
__device__ uint4 g_xf16[NF8];
__device__ uint4 g_f16a[NF8];
__device__ uint4 g_f16b[NF8];
__device__ uint4 g_wt16[WF8];
__device__ uint4 g_wr16[WF8];

// ---------------- helpers ----------------
__device__ __forceinline__ uint32_t smem_u32(const void* p) {
    uint32_t a;
    asm("{ .reg .u64 t; cvta.to.shared.u64 t, %1; cvt.u32.u64 %0, t; }" : "=r"(a) : "l"(p));
    return a;
}
__device__ __forceinline__ void ldsm4(unsigned* r, uint32_t addr) {
    asm volatile("ldmatrix.sync.aligned.m8n8.x4.shared.b16 {%0,%1,%2,%3}, [%4];"
                 : "=r"(r[0]), "=r"(r[1]), "=r"(r[2]), "=r"(r[3]) : "r"(addr));
}
__device__ __forceinline__ void mma_f16(float* d, const unsigned* a, unsigned b0, unsigned b1) {
    asm volatile(
        "mma.sync.aligned.m16n8k16.row.col.f32.f16.f16.f32 "
        "{%0,%1,%2,%3}, {%4,%5,%6,%7}, {%8,%9}, {%0,%1,%2,%3};"
        : "+f"(d[0]), "+f"(d[1]), "+f"(d[2]), "+f"(d[3])
        : "r"(a[0]), "r"(a[1]), "r"(a[2]), "r"(a[3]), "r"(b0), "r"(b1));
}
__device__ __forceinline__ void cpa16(uint32_t dst, const void* src, int src_sz) {
    asm volatile("cp.async.cg.shared.global [%0], [%1], 16, %2;"
                 :: "r"(dst), "l"(src), "r"(src_sz));
}
__device__ __forceinline__ void cpa_commit() {
    asm volatile("cp.async.commit_group;" ::: "memory");
}
__device__ __forceinline__ void cpa_wait0() {
    asm volatile("cp.async.wait_group 0;" ::: "memory");
}
__device__ __forceinline__ unsigned pack_f16(float a, float b) {
    __half2 p = __float22half2_rn(make_float2(a, b));
    return *reinterpret_cast<unsigned*>(&p);
}
__device__ __forceinline__ float decode_gt(const void* p) {
    int iv = *(const int*)p;
    if (iv >= 0 && iv < (1 << 24)) return (float)iv;
    return *(const float*)p;
}
__device__ __forceinline__ void accum8(float* acc, uint4 u, float w) {
    float2 f;
    f = __half22float2(*reinterpret_cast<__half2*>(&u.x)); acc[0] += w * f.x; acc[1] += w * f.y;
    f = __half22float2(*reinterpret_cast<__half2*>(&u.y)); acc[2] += w * f.x; acc[3] += w * f.y;
    f = __half22float2(*reinterpret_cast<__half2*>(&u.z)); acc[4] += w * f.x; acc[5] += w * f.y;
    f = __half22float2(*reinterpret_cast<__half2*>(&u.w)); acc[6] += w * f.x; acc[7] += w * f.y;
}
__device__ __forceinline__ uint4 cvt8_f16(float4 v0, float4 v1) {
    uint4 h;
    h.x = pack_f16(v0.x, v0.y);
    h.y = pack_f16(v0.z, v0.w);
    h.z = pack_f16(v1.x, v1.y);
    h.w = pack_f16(v1.z, v1.w);
    return h;
}

// ---- launch 0: fused conversions + edge pass (measured best in R13/R15 A/B).
// Preconditions (static zero-init on run 1; k_ln re-establishes each run):
//   g_cnt == 0, g_degw == 0, g_tmax_bits == 0, g_scan_arrive == 0.
__global__ void k_prep(const float* __restrict__ x, const float* __restrict__ wt,
                       const float* __restrict__ wr,
                       const int* __restrict__ ei, const float* __restrict__ ts,
                       const void* gt_ptr) {
    int i = blockIdx.x * blockDim.x + threadIdx.x;
    if (i == 0) atomicMax(&g_tmax_bits, __float_as_uint(decode_gt(gt_ptr)));
    // edge work (ts >= 0 so uint order == float order; warp-aggregated max)
    if (i < N_EDGES) {
        float tse = ts[i];
        unsigned mb = __float_as_uint(tse);
#pragma unroll
        for (int o = 16; o; o >>= 1) mb = max(mb, __shfl_xor_sync(0xffffffffu, mb, o));
        if ((threadIdx.x & 31) == 0) atomicMax(&g_tmax_bits, mb);
        float u = expf(TDECAY * tse);
        g_w[i] = u;
        int dst = ei[N_EDGES + i];
        atomicAdd(&g_cnt[dst], 1);
        atomicAdd(&g_degw[dst], u);
    }
    // conversion work
    if (i < NF8) {
        g_xf16[i] = cvt8_f16(((const float4*)x)[2 * i], ((const float4*)x)[2 * i + 1]);
    } else if (i < NF8 + WF8) {
        int j = i - NF8;
        g_wt16[j] = cvt8_f16(((const float4*)wt)[2 * j], ((const float4*)wt)[2 * j + 1]);
    } else if (i < CONV_N) {
        int j = i - NF8 - WF8;
        g_wr16[j] = cvt8_f16(((const float4*)wr)[2 * j], ((const float4*)wr)[2 * j + 1]);
    }
}

// ---- launch 1: fused scan (local scan + cross-block handshake + offsets + dinv) ----
__global__ __launch_bounds__(1024) void k_scan(const void* gt_ptr) {
    __shared__ int sh[1024];
    __shared__ int sps[SCAN_B];
    int b = blockIdx.x, t = threadIdx.x;
    int idx = b * 1000 + t;
    int v = (t < 1000) ? g_cnt[idx] : 0;
    sh[t] = v;
    __syncthreads();
    for (int o = 1; o < 1024; o <<= 1) {
        int x = 0;
        if (t >= o) x = sh[t - o];
        __syncthreads();
        sh[t] += x;
        __syncthreads();
    }
    int local_ex = sh[t] - v;
    if (t == 1023) {
        g_psum[b] = sh[1023];
        __threadfence();
        atomicAdd(&g_scan_arrive, 1);
    }
    if (t == 0) {
        while (atomicAdd(&g_scan_arrive, 0) < SCAN_B) {}
        __threadfence();
    }
    __syncthreads();
    if (t < SCAN_B) sps[t] = g_psum[t];
    __syncthreads();
    if (t < 1000) {
        int off = 0, tot = 0;
#pragma unroll
        for (int q = 0; q < SCAN_B; q++) {
            int p = sps[q];
            if (q < b) off += p;
            tot += p;
        }
        int val = local_ex + off;
        g_rowptr[idx] = val;
        g_cursor[idx] = val;
        if (idx == 0) g_rowptr[N_NODES] = tot;
        float tmax = __uint_as_float(g_tmax_bits);
        float sc = expf(-TDECAY * tmax);
        float self_w = expf(-TDECAY * (tmax - decode_gt(gt_ptr)));
        float totw = g_degw[idx] * sc + self_w;
        g_dinv[idx] = (totw > 0.f) ? (1.f / sqrtf(totw)) : 0.f;
    }
}

// ---- launch 2: CSR fill with fused weights ----
__global__ void k_fill(const int* __restrict__ ei) {
    int e = blockIdx.x * blockDim.x + threadIdx.x;
    if (e >= N_EDGES) return;
    float tmax = __uint_as_float(g_tmax_bits);
    float sc = DT * expf(-TDECAY * tmax);
    int src = ei[e], dst = ei[N_EDGES + e];
    int p = atomicAdd(&g_cursor[dst], 1);
    float ew = g_dinv[src] * g_w[e] * sc * g_dinv[dst];
    g_edge[p] = make_int2(src, __float_as_int(ew));
}

// ---- launches 3-7: fp16 diffusion SpMM, 4 nodes per 256-thread block.
// 5 separate launches: HW block scheduling balances skewed degrees better
// than a persistent static partition (measured +47us regression in R15).
__global__ __launch_bounds__(256) void k_spmm16(int step, const void* gt_ptr) {
    const uint4* __restrict__ hin = (step == 0) ? g_xf16 : ((step & 1) ? g_f16a : g_f16b);
    uint4* hout = (step & 1) ? g_f16b : g_f16a;
    int n = blockIdx.x * 4 + (threadIdx.x >> 6);   // 64-thread group per node
    int t = threadIdx.x & 63;

    float tmax = __uint_as_float(g_tmax_bits);
    float self_w = expf(-TDECAY * (tmax - decode_gt(gt_ptr)));
    float dv = g_dinv[n];
    float coef = (1.f - DT) + DT * self_w * dv * dv;

    size_t self_idx = (size_t)n * 64 + t;
    float acc[8];
    {
        uint4 su = hin[self_idx];
        float2 f;
        f = __half22float2(*reinterpret_cast<__half2*>(&su.x)); acc[0] = coef * f.x; acc[1] = coef * f.y;
        f = __half22float2(*reinterpret_cast<__half2*>(&su.y)); acc[2] = coef * f.x; acc[3] = coef * f.y;
        f = __half22float2(*reinterpret_cast<__half2*>(&su.z)); acc[4] = coef * f.x; acc[5] = coef * f.y;
        f = __half22float2(*reinterpret_cast<__half2*>(&su.w)); acc[6] = coef * f.x; acc[7] = coef * f.y;
    }

    int j = g_rowptr[n], end = g_rowptr[n + 1];
    for (; j + 8 <= end; j += 8) {
        int2 e[8]; uint4 u[8];
#pragma unroll
        for (int q = 0; q < 8; q++) e[q] = g_edge[j + q];
#pragma unroll
        for (int q = 0; q < 8; q++) u[q] = hin[(size_t)e[q].x * 64 + t];
#pragma unroll
        for (int q = 0; q < 8; q++) accum8(acc, u[q], __int_as_float(e[q].y));
    }
    for (; j + 2 <= end; j += 2) {
        int2 e0 = g_edge[j], e1 = g_edge[j + 1];
        uint4 u0 = hin[(size_t)e0.x * 64 + t];
        uint4 u1 = hin[(size_t)e1.x * 64 + t];
        accum8(acc, u0, __int_as_float(e0.y));
        accum8(acc, u1, __int_as_float(e1.y));
    }
    if (j < end) {
        int2 e = g_edge[j];
        uint4 u = hin[(size_t)e.x * 64 + t];
        accum8(acc, u, __int_as_float(e.y));
    }

    uint4 o;
    o.x = pack_f16(acc[0], acc[1]);
    o.y = pack_f16(acc[2], acc[3]);
    o.z = pack_f16(acc[4], acc[5]);
    o.w = pack_f16(acc[6], acc[7]);
    hout[self_idx] = o;
}

// ---- chunk loader: A + B fp16 tiles, 128 rows x 32 halfs, cp.async ----
__device__ __forceinline__ void load_chunk(uint32_t sb,
                                           const __half* __restrict__ A,
                                           const __half* __restrict__ B,
                                           int arow0, int brow0, int k0, int t) {
#pragma unroll
    for (int it = 0; it < 2; it++) {
        int s = t + it * 256;
        int row = s >> 2, q = s & 3;
        uint32_t doff = row * ROWB + q * 16;
        int ar = arow0 + row;
        int ok = (ar < N_NODES) ? 16 : 0;
        size_t aoff = (size_t)(ok ? ar : 0) * F + k0 + q * 8;
        size_t boff = (size_t)(brow0 + row) * F + k0 + q * 8;
        cpa16(sb + doff, A + aoff, ok);
        cpa16(sb + TSZ + doff, B + boff, 16);
    }
}

// ---- launch 8: fused dual GEMM fp16: out = relu(h@Wt^T + b) + x@Wr^T ----
// occupancy 2 (NOT 4): the 64-float accumulator file needs ~128 regs; capping at
// 64 regs (occ 4) spills accumulators into the MMA loop — measured regression R8.
__global__ __launch_bounds__(256, 2) void k_gemm2(const float* __restrict__ bias,
                                                  float* __restrict__ out) {
    extern __shared__ char smd[];
    int t = threadIdx.x, lane = t & 31, wid = t >> 5;
    int wm = wid >> 1, wn = wid & 1;
    int bm = blockIdx.x, bn = blockIdx.y;

    int lr8 = lane & 7, lt = lane >> 3;
    int row_off = lr8 + (lt & 1) * 8;
    int col_off = (lt >> 1) * 8;

    const __half* H = (const __half*)g_f16a;     // diffusion output (step 4 -> g_f16a)
    const __half* X = (const __half*)g_xf16;
    const __half* T = (const __half*)g_wt16;
    const __half* R = (const __half*)g_wr16;

    float acc[2][8][4];
#pragma unroll
    for (int i = 0; i < 2; i++)
#pragma unroll
        for (int j = 0; j < 8; j++)
#pragma unroll
            for (int q = 0; q < 4; q++) acc[i][j][q] = 0.f;

    uint32_t sbase = smem_u32(smd);
    int am0 = bm * TILE_M, bn0 = bn * TILE_N;

    load_chunk(sbase, H, T, am0, bn0, 0, t);
    cpa_commit();

    for (int c = 0; c < 2 * NCH1; c++) {
        cpa_wait0();
        __syncthreads();
        if (c + 1 < 2 * NCH1) {
            int cn = c + 1;
            uint32_t nsb = sbase + (cn & 1) * BUF_SZ;
            if (cn < NCH1)
                load_chunk(nsb, H, T, am0, bn0, cn * KCHUNK, t);
            else
                load_chunk(nsb, X, R, am0, bn0, (cn - NCH1) * KCHUNK, t);
            cpa_commit();
        }
        uint32_t sb = sbase + (c & 1) * BUF_SZ;
#pragma unroll
        for (int ks = 0; ks < 2; ks++) {
            unsigned af[2][4];
#pragma unroll
            for (int mt = 0; mt < 2; mt++)
                ldsm4(af[mt], sb + (wm * 32 + mt * 16 + row_off) * ROWB
                                 + (ks * 16 + col_off) * 2);
            unsigned bf[4][4];
#pragma unroll
            for (int pr = 0; pr < 4; pr++)
                ldsm4(bf[pr], sb + TSZ + (wn * 64 + pr * 16 + row_off) * ROWB
                                 + (ks * 16 + col_off) * 2);
#pragma unroll
            for (int mt = 0; mt < 2; mt++)
#pragma unroll
                for (int nt = 0; nt < 8; nt++) {
                    int pr = nt >> 1, h = nt & 1;
                    mma_f16(acc[mt][nt], af[mt], bf[pr][h], bf[pr][h + 2]);
                }
        }
        if (c == NCH1 - 1) {
            // acc = relu(acc + bias); then accumulate x@Wr^T into same registers
            int cb = bn0 + wn * 64 + 2 * (lane & 3);
#pragma unroll
            for (int nt = 0; nt < 8; nt++) {
                float b0 = __ldg(bias + cb + nt * 8);
                float b1 = __ldg(bias + cb + nt * 8 + 1);
#pragma unroll
                for (int mt = 0; mt < 2; mt++) {
                    acc[mt][nt][0] = fmaxf(acc[mt][nt][0] + b0, 0.f);
                    acc[mt][nt][1] = fmaxf(acc[mt][nt][1] + b1, 0.f);
                    acc[mt][nt][2] = fmaxf(acc[mt][nt][2] + b0, 0.f);
                    acc[mt][nt][3] = fmaxf(acc[mt][nt][3] + b1, 0.f);
                }
            }
        }
        __syncthreads();
    }

    int rbase = am0 + wm * 32 + (lane >> 2);
    int cbase = bn0 + wn * 64 + 2 * (lane & 3);
#pragma unroll
    for (int mt = 0; mt < 2; mt++) {
#pragma unroll
        for (int h = 0; h < 2; h++) {
            int row = rbase + mt * 16 + h * 8;
            if (row >= N_NODES) continue;
            float* crow = out + (size_t)row * F;
#pragma unroll
            for (int nt = 0; nt < 8; nt++) {
                int col = cbase + nt * 8;
                *(float2*)(crow + col) = make_float2(acc[mt][nt][2 * h], acc[mt][nt][2 * h + 1]);
            }
        }
    }
}

// ---- launch 9: row LayerNorm in place + per-run state reset ----
__global__ __launch_bounds__(128) void k_ln(float* __restrict__ out,
                                            const float* __restrict__ gamma,
                                            const float* __restrict__ beta) {
    int n = blockIdx.x;
    int t = threadIdx.x;
    // reset per-run state (all consumers are upstream of this launch)
    if (t == 0) {
        g_cnt[n] = 0;
        g_degw[n] = 0.f;
        if (n == 0) { g_tmax_bits = 0u; g_scan_arrive = 0; }
    }
    float4* row = (float4*)(out + (size_t)n * F);
    float4 v = row[t];
    float s = v.x + v.y + v.z + v.w;
    float q = v.x * v.x + v.y * v.y + v.z * v.z + v.w * v.w;
#pragma unroll
    for (int o = 16; o; o >>= 1) {
        s += __shfl_xor_sync(0xffffffffu, s, o);
        q += __shfl_xor_sync(0xffffffffu, q, o);
    }
    __shared__ float shs[4], shq[4];
    int w = t >> 5, l = t & 31;
    if (l == 0) { shs[w] = s; shq[w] = q; }
    __syncthreads();
    s = shs[0] + shs[1] + shs[2] + shs[3];
    q = shq[0] + shq[1] + shq[2] + shq[3];
    float mu = s * (1.f / F);
    float var = q * (1.f / F) - mu * mu;
    float inv = rsqrtf(var + LN_EPS);
    float4 gv = ((const float4*)gamma)[t];
    float4 bv = ((const float4*)beta)[t];
    v.x = (v.x - mu) * inv * gv.x + bv.x;
    v.y = (v.y - mu) * inv * gv.y + bv.y;
    v.z = (v.z - mu) * inv * gv.z + bv.z;
    v.w = (v.w - mu) * inv * gv.w + bv.w;
    row[t] = v;
}

extern "C" void kernel_launch(void* const* d_in, const int* in_sizes, int n_in,
                              void* d_out, int out_size) {
    const float* x = (const float*)d_in[0];
    const int* ei = (const int*)d_in[1];
    const float* ts = (const float*)d_in[2];
    const float* W_t = (const float*)d_in[3];
    const float* b_t = (const float*)d_in[4];
    const float* W_r = (const float*)d_in[5];
    const float* gamma = (const float*)d_in[6];
    const float* beta = (const float*)d_in[7];
    const void* gt = d_in[8];
    float* out = (float*)d_out;

    cudaFuncSetAttribute(k_gemm2, cudaFuncAttributeMaxDynamicSharedMemorySize, SMEM_DYN);

    k_prep<<<(CONV_N + 255) / 256, 256>>>(x, W_t, W_r, ei, ts, gt);  // 0
    k_scan<<<SCAN_B, 1024>>>(gt);                                    // 1
    k_fill<<<N_EDGES / 256, 256>>>(ei);                              // 2
    for (int s = 0; s < 5; s++)                                      // 3..7
        k_spmm16<<<N_NODES / 4, 256>>>(s, gt);
    dim3 gg((N_NODES + TILE_M - 1) / TILE_M, F / TILE_N);
    k_gemm2<<<gg, 256, SMEM_DYN>>>(b_t, out);                        // 8
    k_ln<<<N_NODES, 128>>>(out, gamma, beta);                        // 9
}